// round 11
// baseline (speedup 1.0000x reference)
#include <cuda_runtime.h>
#include <cuda_bf16.h>
#include <math.h>
#include <stdint.h>

// Problem constants
#define D512 512
#define T256 256
#define NROWS 2048          // T * TOPK
#define MAXH 2560
#define NEXP 16
#define NCLS 4096
#define TOPK 8

// ---------------- scratch (device globals; no allocation allowed) ----------
__device__ float g_h1[T256 * D512];
__device__ float g_h2[T256 * 256];
__device__ float g_scores[T256 * NCLS];
__device__ float g_lin[NROWS * D512];
__device__ float g_xin[NROWS * D512];
__device__ float g_hid[NROWS * MAXH];
__device__ float g_mlpout[NROWS * D512];
__device__ float g_z[NROWS * D512];
__device__ int   g_preE[NROWS];
__device__ int   g_mlpE[NROWS];
__device__ int   g_postE[NROWS];
__device__ float g_wgt[NROWS];
__device__ int   g_cnt[48];
__device__ int   g_cur[48];
__device__ int   g_off[51];
__device__ int   g_permP[NROWS];
__device__ int   g_permM[NROWS];
__device__ int   g_permQ[NROWS];
// probe routing: identity perm, uniform 128-row segments (diagnostic only)
__device__ int   g_pperm[NROWS];
__device__ int   g_poff[17];

// ---------------- activations ----------------
__device__ __forceinline__ float act_apply(int a, float v) {
    switch (a & 3) {
        case 0:  return 0.5f * v * (1.0f + erff(v * 0.70710678118654752f));
        case 1:  return fmaxf(v, 0.0f);
        case 2:  return tanhf(v);
        default: return v * (1.0f / (1.0f + expf(-v)));
    }
}

__device__ __forceinline__ uint32_t to_tf32_u(float x) {
    uint32_t u;
    asm("cvt.rna.tf32.f32 %0, %1;" : "=r"(u) : "f"(x));
    return u;
}

__device__ __forceinline__ void mma_tf32(float c[4], const uint32_t a[4], const uint32_t b[2]) {
    asm volatile(
        "mma.sync.aligned.m16n8k8.row.col.f32.tf32.tf32.f32 "
        "{%0,%1,%2,%3}, {%4,%5,%6,%7}, {%8,%9}, {%0,%1,%2,%3};"
        : "+f"(c[0]), "+f"(c[1]), "+f"(c[2]), "+f"(c[3])
        : "r"(a[0]), "r"(a[1]), "r"(a[2]), "r"(a[3]), "r"(b[0]), "r"(b[1]));
}

__device__ __forceinline__ void cp16(uint32_t smem_addr, const void* gptr, bool valid) {
    int sz = valid ? 16 : 0;
    asm volatile("cp.async.ca.shared.global [%0], [%1], 16, %2;"
                 :: "r"(smem_addr), "l"(gptr), "r"(sz));
}
__device__ __forceinline__ void cp_commit() {
    asm volatile("cp.async.commit_group;");
}
template<int N>
__device__ __forceinline__ void cp_wait() {
    asm volatile("cp.async.wait_group %0;" :: "n"(N));
}

// ================= fp32 FFMA GEMM (router only: precision-critical) ========
#define BM 32
#define BN 128
#define BK 16

template<int ACT>
__global__ __launch_bounds__(256)
void gemm_k(const float* __restrict__ X, int ldx,
            const float* __restrict__ W, int ldw,
            const float* __restrict__ bias,
            float* __restrict__ Y, int ldy,
            int M, int K)
{
    int n0 = blockIdx.x * BN;
    int m0 = blockIdx.y * BM;
    if (m0 >= M) return;

    __shared__ float Xs[BK][BM];
    __shared__ float Ws[BK][BN];

    int tid = threadIdx.x;
    int tx = tid & 31, ty = tid >> 5;
    int c0 = tx * 4, r0 = ty * 4;

    float acc[4][4];
#pragma unroll
    for (int i = 0; i < 4; i++)
#pragma unroll
        for (int j = 0; j < 4; j++) acc[i][j] = 0.0f;

    int xm = tid >> 2, xk = (tid & 3) * 4;
    const float* xp = X + (long)(m0 + xm) * ldx;
    bool xok = (tid < 128) && (m0 + xm < M);

    for (int k0 = 0; k0 < K; k0 += BK) {
        const float* wp = W + (long)(k0 + ty) * ldw + n0 + c0;
        float4 w0 = *(const float4*)wp;
        float4 w1 = *(const float4*)(wp + (long)8 * ldw);
        float4 xv = make_float4(0.f, 0.f, 0.f, 0.f);
        if (xok) xv = *(const float4*)(xp + k0 + xk);

        *(float4*)&Ws[ty][c0]     = w0;
        *(float4*)&Ws[ty + 8][c0] = w1;
        if (tid < 128) {
            Xs[xk + 0][xm] = xv.x; Xs[xk + 1][xm] = xv.y;
            Xs[xk + 2][xm] = xv.z; Xs[xk + 3][xm] = xv.w;
        }
        __syncthreads();

#pragma unroll
        for (int kk = 0; kk < BK; kk++) {
            float4 a = *(const float4*)&Xs[kk][r0];
            float4 b = *(const float4*)&Ws[kk][c0];
            acc[0][0] += a.x * b.x; acc[0][1] += a.x * b.y; acc[0][2] += a.x * b.z; acc[0][3] += a.x * b.w;
            acc[1][0] += a.y * b.x; acc[1][1] += a.y * b.y; acc[1][2] += a.y * b.z; acc[1][3] += a.y * b.w;
            acc[2][0] += a.z * b.x; acc[2][1] += a.z * b.y; acc[2][2] += a.z * b.z; acc[2][3] += a.z * b.w;
            acc[3][0] += a.w * b.x; acc[3][1] += a.w * b.y; acc[3][2] += a.w * b.z; acc[3][3] += a.w * b.w;
        }
        __syncthreads();
    }

    float4 bb = *(const float4*)(bias + n0 + c0);
#pragma unroll
    for (int i = 0; i < 4; i++) {
        int r = m0 + r0 + i;
        if (r >= M) continue;
        float4 o;
        o.x = acc[i][0] + bb.x; o.y = acc[i][1] + bb.y;
        o.z = acc[i][2] + bb.z; o.w = acc[i][3] + bb.w;
        if (ACT == 1) {
            o.x = act_apply(0, o.x); o.y = act_apply(0, o.y);
            o.z = act_apply(0, o.z); o.w = act_apply(0, o.w);
        }
        *(float4*)(Y + (long)r * ldy + n0 + c0) = o;
    }
}

// ===== tf32 tensor-core grouped GEMM, 4-stage cp.async, single-sync loop ===
#define STAGES 4
#define XPAD 28
#define WPAD 132
#define XS_SZ (64 * XPAD)
#define WS_SZ (16 * WPAD)
#define TC_SMEM_BYTES (STAGES * (XS_SZ + WS_SZ) * (int)sizeof(float) + 64 * (int)sizeof(int))

template<int ACT, int NKMODE>
__global__ __launch_bounds__(256)
void gemm_tc(const float* __restrict__ X, int ldx, int xshift,
             const float* __restrict__ W, long wstride, int ldw,
             const float* __restrict__ bias, int bstride,
             float* __restrict__ Y, int ldy,
             int K,
             const int* __restrict__ perm, const int* __restrict__ segoff)
{
    int e  = blockIdx.z;
    int n0 = blockIdx.x * 128;
    int he = 512 * (2 + (e >> 2));
    if (NKMODE == 1 && n0 >= he) return;
    int Keff = (NKMODE == 2) ? he : K;

    int segs = segoff[e], sege = segoff[e + 1];
    int m0 = segs + blockIdx.y * 64;
    if (m0 >= sege) return;

    extern __shared__ float sm[];
    float* XsB = sm;
    float* WsB = sm + STAGES * XS_SZ;
    int*   rows = (int*)(sm + STAGES * (XS_SZ + WS_SZ));

    int tid = threadIdx.x;
    if (tid < 64) {
        int p = m0 + tid;
        rows[tid] = (p < sege) ? perm[p] : -1;
    }
    __syncthreads();

    const float* Wb = W + (long)e * wstride;

    int wrow = tid >> 5, wc4 = (tid & 31) * 4;
    int xrow = tid >> 2, xc4 = (tid & 3) * 4;
    int xr = rows[xrow];
    const float* xp = X + (long)((xr >= 0 ? xr : 0) >> xshift) * ldx;
    bool xok = (xr >= 0);

    uint32_t xs_dst[STAGES], ws_dst0[STAGES], ws_dst1[STAGES];
#pragma unroll
    for (int s = 0; s < STAGES; s++) {
        xs_dst[s]  = (uint32_t)__cvta_generic_to_shared(&XsB[s * XS_SZ + xrow * XPAD + xc4]);
        ws_dst0[s] = (uint32_t)__cvta_generic_to_shared(&WsB[s * WS_SZ + wrow * WPAD + wc4]);
        ws_dst1[s] = (uint32_t)__cvta_generic_to_shared(&WsB[s * WS_SZ + (wrow + 8) * WPAD + wc4]);
    }

    int nk = Keff >> 4;

#pragma unroll
    for (int s = 0; s < STAGES - 1; s++) {
        if (s < nk) {
            int k0 = s << 4;
            cp16(ws_dst0[s], Wb + (long)(k0 + wrow) * ldw + n0 + wc4, true);
            cp16(ws_dst1[s], Wb + (long)(k0 + wrow + 8) * ldw + n0 + wc4, true);
            cp16(xs_dst[s],  xp + k0 + xc4, xok);
        }
        cp_commit();
    }

    int lane = tid & 31, warp = tid >> 5;
    int wm = warp >> 2, wn = warp & 3;
    int lr = lane >> 2, lc = lane & 3;

    float c[2][4][4];
#pragma unroll
    for (int i = 0; i < 2; i++)
#pragma unroll
        for (int j = 0; j < 4; j++)
#pragma unroll
            for (int q = 0; q < 4; q++) c[i][j][q] = 0.0f;

    for (int t = 0; t < nk; t++) {
        cp_wait<STAGES - 2>();
        __syncthreads();

        int tn = t + STAGES - 1;
        if (tn < nk) {
            int k0 = tn << 4;
            int s = tn % STAGES;
            cp16(ws_dst0[s], Wb + (long)(k0 + wrow) * ldw + n0 + wc4, true);
            cp16(ws_dst1[s], Wb + (long)(k0 + wrow + 8) * ldw + n0 + wc4, true);
            cp16(xs_dst[s],  xp + k0 + xc4, xok);
        }
        cp_commit();

        int buf = t % STAGES;
        const float* Xb = XsB + buf * XS_SZ;
        const float* Wv = WsB + buf * WS_SZ;
#pragma unroll
        for (int ks = 0; ks < 16; ks += 8) {
            uint32_t a[2][4], b[4][2];
#pragma unroll
            for (int i = 0; i < 2; i++) {
                int bm = wm * 32 + i * 16;
                a[i][0] = to_tf32_u(Xb[(bm + lr    ) * XPAD + ks + lc    ]);
                a[i][1] = to_tf32_u(Xb[(bm + lr + 8) * XPAD + ks + lc    ]);
                a[i][2] = to_tf32_u(Xb[(bm + lr    ) * XPAD + ks + lc + 4]);
                a[i][3] = to_tf32_u(Xb[(bm + lr + 8) * XPAD + ks + lc + 4]);
            }
#pragma unroll
            for (int j = 0; j < 4; j++) {
                int bn = wn * 32 + j * 8 + lr;
                b[j][0] = to_tf32_u(Wv[(ks + lc    ) * WPAD + bn]);
                b[j][1] = to_tf32_u(Wv[(ks + lc + 4) * WPAD + bn]);
            }
#pragma unroll
            for (int i = 0; i < 2; i++)
#pragma unroll
                for (int j = 0; j < 4; j++)
                    mma_tf32(c[i][j], a[i], b[j]);
        }
    }

#pragma unroll
    for (int j = 0; j < 4; j++) {
        int n = n0 + wn * 32 + j * 8 + 2 * lc;
        float2 bb = *(const float2*)(bias + (long)e * bstride + n);
#pragma unroll
        for (int i = 0; i < 2; i++) {
            int base = wm * 32 + i * 16 + lr;
            int ra = rows[base];
            int rb = rows[base + 8];
            if (ra >= 0) {
                float o0 = c[i][j][0] + bb.x, o1 = c[i][j][1] + bb.y;
                if (ACT == 2) { o0 = act_apply(e, o0); o1 = act_apply(e, o1); }
                *(float2*)(Y + (long)ra * ldy + n) = make_float2(o0, o1);
            }
            if (rb >= 0) {
                float o0 = c[i][j][2] + bb.x, o1 = c[i][j][3] + bb.y;
                if (ACT == 2) { o0 = act_apply(e, o0); o1 = act_apply(e, o1); }
                *(float2*)(Y + (long)rb * ldy + n) = make_float2(o0, o1);
            }
        }
    }
}

// ---------------- softmax + top-8 + route decompose ----------------
__global__ __launch_bounds__(256)
void topk_k(const float* __restrict__ scores, const float* __restrict__ temp,
            int* __restrict__ preE, int* __restrict__ mlpE, int* __restrict__ postE,
            float* __restrict__ wgt, int* __restrict__ cnt)
{
    int t = blockIdx.x;
    __shared__ float s[NCLS];
    __shared__ float rv[256];
    __shared__ int   ri[256];
    __shared__ float selv[TOPK];
    __shared__ int   seli[TOPK];

    int tid = threadIdx.x;
    float invT = 1.0f / temp[0];
    for (int i = tid; i < NCLS; i += 256) s[i] = scores[(long)t * NCLS + i] * invT;
    __syncthreads();

    float m = -INFINITY;
    for (int i = tid; i < NCLS; i += 256) m = fmaxf(m, s[i]);
    rv[tid] = m; __syncthreads();
    for (int o = 128; o > 0; o >>= 1) { if (tid < o) rv[tid] = fmaxf(rv[tid], rv[tid + o]); __syncthreads(); }
    m = rv[0]; __syncthreads();

    float sum = 0.0f;
    for (int i = tid; i < NCLS; i += 256) sum += expf(s[i] - m);
    rv[tid] = sum; __syncthreads();
    for (int o = 128; o > 0; o >>= 1) { if (tid < o) rv[tid] += rv[tid + o]; __syncthreads(); }
    float denom = rv[0]; __syncthreads();

    for (int it = 0; it < TOPK; it++) {
        float bv = -INFINITY; int bi = -1;
        for (int i = tid; i < NCLS; i += 256) {
            bool used = false;
            for (int j = 0; j < it; j++) if (seli[j] == i) used = true;
            if (!used) {
                float v = s[i];
                if (v > bv || (v == bv && (unsigned)i < (unsigned)bi)) { bv = v; bi = i; }
            }
        }
        rv[tid] = bv; ri[tid] = bi; __syncthreads();
        for (int o = 128; o > 0; o >>= 1) {
            if (tid < o) {
                if (rv[tid + o] > rv[tid] ||
                    (rv[tid + o] == rv[tid] && (unsigned)ri[tid + o] < (unsigned)ri[tid])) {
                    rv[tid] = rv[tid + o]; ri[tid] = ri[tid + o];
                }
            }
            __syncthreads();
        }
        if (tid == 0) { selv[it] = rv[0]; seli[it] = ri[0]; }
        __syncthreads();
    }

    if (tid < TOPK) {
        int idx = seli[tid];
        float p = expf(selv[tid] - m) / denom;
        float w = (p >= 1e-6f) ? p : 0.0f;
        int pe = idx >> 8;
        int rem = idx & 255;
        int me = rem >> 4;
        int qe = rem & 15;
        int r = t * TOPK + tid;
        preE[r] = pe; mlpE[r] = me; postE[r] = qe; wgt[r] = w;
        atomicAdd(&cnt[pe], 1);
        atomicAdd(&cnt[16 + me], 1);
        atomicAdd(&cnt[32 + qe], 1);
    }
}

__global__ void zero_k(int* cnt, int* cur, int* pperm, int* poff) {
    int i = blockIdx.x * blockDim.x + threadIdx.x;
    if (i < 48) { cnt[i] = 0; cur[i] = 0; }
    if (i < 17) poff[i] = i * 128;
    if (i < NROWS) pperm[i] = i;
}

__global__ void scan_k(const int* __restrict__ cnt, int* __restrict__ off) {
    if (threadIdx.x == 0) {
        for (int gp = 0; gp < 3; gp++) {
            int a = 0;
            for (int i = 0; i < 16; i++) { off[gp * 17 + i] = a; a += cnt[gp * 16 + i]; }
            off[gp * 17 + 16] = a;
        }
    }
}

__global__ void scatter_k(const int* __restrict__ preE, const int* __restrict__ mlpE,
                          const int* __restrict__ postE, const int* __restrict__ off,
                          int* __restrict__ cur,
                          int* __restrict__ permP, int* __restrict__ permM, int* __restrict__ permQ)
{
    int i = blockIdx.x * blockDim.x + threadIdx.x;
    if (i >= NROWS) return;
    int e, p;
    e = preE[i];  p = off[e]       + atomicAdd(&cur[e],      1); permP[p] = i;
    e = mlpE[i];  p = off[17 + e]  + atomicAdd(&cur[16 + e], 1); permM[p] = i;
    e = postE[i]; p = off[34 + e]  + atomicAdd(&cur[32 + e], 1); permQ[p] = i;
}

// ---------------- row layernorm (+optional act) ----------------
template<int MODE>
__global__ __launch_bounds__(256)
void ln_k(const float* __restrict__ in, float* __restrict__ out,
          const int* __restrict__ eArr, const float* __restrict__ g, const float* __restrict__ be)
{
    int row = blockIdx.x;
    int e = eArr[row];
    const float* xp = in + (long)row * D512;
    float* yp = out + (long)row * D512;
    int tid = threadIdx.x;
    float v0 = xp[tid], v1 = xp[tid + 256];
    if (MODE == 1 && (e & 1)) { yp[tid] = v0; yp[tid + 256] = v1; return; }

    __shared__ float red[256];
    red[tid] = v0 + v1; __syncthreads();
    for (int o = 128; o > 0; o >>= 1) { if (tid < o) red[tid] += red[tid + o]; __syncthreads(); }
    float mu = red[0] * (1.0f / 512.0f);
    __syncthreads();
    float d0 = v0 - mu, d1 = v1 - mu;
    red[tid] = d0 * d0 + d1 * d1; __syncthreads();
    for (int o = 128; o > 0; o >>= 1) { if (tid < o) red[tid] += red[tid + o]; __syncthreads(); }
    float rstd = rsqrtf(red[0] * (1.0f / 512.0f) + 1e-5f);

    float y0 = d0 * rstd * g[e * D512 + tid]       + be[e * D512 + tid];
    float y1 = d1 * rstd * g[e * D512 + tid + 256] + be[e * D512 + tid + 256];
    if (MODE == 0) { y0 = act_apply(e, y0); y1 = act_apply(e, y1); }
    yp[tid] = y0; yp[tid + 256] = y1;
}

// ---------------- weighted combine ----------------
__global__ void final_k(const float* __restrict__ z, const float* __restrict__ wgt,
                        float* __restrict__ out)
{
    int t = blockIdx.x, d = threadIdx.x;
    float acc = 0.0f;
#pragma unroll
    for (int k = 0; k < TOPK; k++) {
        int r = t * TOPK + k;
        acc += wgt[r] * z[(long)r * D512 + d];
    }
    out[(long)t * D512 + d] = acc;
}

// ---------------- launch ----------------
template <typename Tv>
static float* symf(Tv& v) { void* p = nullptr; cudaGetSymbolAddress(&p, v); return (float*)p; }
template <typename Tv>
static int* symi(Tv& v) { void* p = nullptr; cudaGetSymbolAddress(&p, v); return (int*)p; }

extern "C" void kernel_launch(void* const* d_in, const int* in_sizes, int n_in,
                              void* d_out, int out_size)
{
    const float* x      = (const float*)d_in[0];
    const float* r_w1   = (const float*)d_in[1];
    const float* r_b1   = (const float*)d_in[2];
    const float* r_w2   = (const float*)d_in[3];
    const float* r_b2   = (const float*)d_in[4];
    const float* r_w3   = (const float*)d_in[5];
    const float* r_b3   = (const float*)d_in[6];
    const float* temp   = (const float*)d_in[7];
    const float* pre_w  = (const float*)d_in[8];
    const float* pre_b  = (const float*)d_in[9];
    const float* pre_g  = (const float*)d_in[10];
    const float* pre_be = (const float*)d_in[11];
    const float* mlp_w1 = (const float*)d_in[12];
    const float* mlp_b1 = (const float*)d_in[13];
    const float* mlp_w2 = (const float*)d_in[14];
    const float* mlp_b2 = (const float*)d_in[15];
    const float* post_w = (const float*)d_in[16];
    const float* post_b = (const float*)d_in[17];
    const float* post_g = (const float*)d_in[18];
    const float* post_be= (const float*)d_in[19];
    float* out = (float*)d_out;

    float* h1     = symf(g_h1);
    float* h2     = symf(g_h2);
    float* scores = symf(g_scores);
    float* lin    = symf(g_lin);
    float* xin    = symf(g_xin);
    float* hid    = symf(g_hid);
    float* mout   = symf(g_mlpout);
    float* zbuf   = symf(g_z);
    float* wgt    = symf(g_wgt);
    int* preE  = symi(g_preE);
    int* mlpE  = symi(g_mlpE);
    int* postE = symi(g_postE);
    int* cnt   = symi(g_cnt);
    int* cur   = symi(g_cur);
    int* off   = symi(g_off);
    int* permP = symi(g_permP);
    int* permM = symi(g_permM);
    int* permQ = symi(g_permQ);
    int* pperm = symi(g_pperm);
    int* poff  = symi(g_poff);

    cudaFuncSetAttribute(gemm_tc<0, 0>, cudaFuncAttributeMaxDynamicSharedMemorySize, TC_SMEM_BYTES);
    cudaFuncSetAttribute(gemm_tc<2, 1>, cudaFuncAttributeMaxDynamicSharedMemorySize, TC_SMEM_BYTES);
    cudaFuncSetAttribute(gemm_tc<0, 2>, cudaFuncAttributeMaxDynamicSharedMemorySize, TC_SMEM_BYTES);

    // 1: zero counters + build probe identity routing
    zero_k<<<8, 256>>>(cnt, cur, pperm, poff);

    // 2,3: router first two stages (fp32)
    gemm_k<1><<<dim3(4, 8, 1), 256>>>(x, 512, r_w1, 512, r_b1, h1, 512, 256, 512);
    gemm_k<1><<<dim3(2, 8, 1), 256>>>(h1, 512, r_w2, 256, r_b2, h2, 256, 256, 512);

    // 4: DIAGNOSTIC PROBE — mlp1-shaped gemm_tc on identity routing, landing
    // in the deterministic ncu capture slot (4th launch). Writes g_hid, which
    // the real mlp1 launch fully overwrites for every consumed element.
    gemm_tc<2, 1><<<dim3(20, 32, 16), 256, TC_SMEM_BYTES>>>(
        xin, 512, 0, mlp_w1, 512L * 2560, 2560, mlp_b1, 2560, hid, 2560, 512, pperm, poff);

    // 5: router scores
    gemm_k<0><<<dim3(32, 8, 1), 256>>>(h2, 256, r_w3, 4096, r_b3, scores, 4096, 256, 256);

    // routing
    topk_k<<<256, 256>>>(scores, temp, preE, mlpE, postE, wgt, cnt);
    scan_k<<<1, 32>>>(cnt, off);
    scatter_k<<<8, 256>>>(preE, mlpE, postE, off, cur, permP, permM, permQ);

    // pre experts: linear -> LN + act
    gemm_tc<0, 0><<<dim3(4, 32, 16), 256, TC_SMEM_BYTES>>>(
        x, 512, 3, pre_w, 512L * 512, 512, pre_b, 512, lin, 512, 512, permP, off);
    ln_k<0><<<2048, 256>>>(lin, xin, preE, pre_g, pre_be);

    // mlp experts
    gemm_tc<2, 1><<<dim3(20, 32, 16), 256, TC_SMEM_BYTES>>>(
        xin, 512, 0, mlp_w1, 512L * 2560, 2560, mlp_b1, 2560, hid, 2560, 512, permM, off + 17);
    gemm_tc<0, 2><<<dim3(4, 32, 16), 256, TC_SMEM_BYTES>>>(
        hid, 2560, 0, mlp_w2, 2560L * 512, 512, mlp_b2, 512, mout, 512, 0, permM, off + 17);

    // post experts: linear -> optional LN
    gemm_tc<0, 0><<<dim3(4, 32, 16), 256, TC_SMEM_BYTES>>>(
        mout, 512, 0, post_w, 512L * 512, 512, post_b, 512, lin, 512, 512, permQ, off + 34);
    ln_k<1><<<2048, 256>>>(lin, zbuf, postE, post_g, post_be);

    // weighted combine
    final_k<<<256, 512>>>(zbuf, wgt, out);
    (void)in_sizes; (void)n_in; (void)out_size;
}

// round 12
// speedup vs baseline: 1.2047x; 1.2047x over previous
#include <cuda_runtime.h>
#include <cuda_bf16.h>
#include <math.h>
#include <stdint.h>

// Problem constants
#define D512 512
#define T256 256
#define NROWS 2048          // T * TOPK
#define MAXH 2560
#define NEXP 16
#define NCLS 4096
#define TOPK 8

// ---------------- scratch (device globals; no allocation allowed) ----------
__device__ float g_h1[T256 * D512];
__device__ float g_h2[T256 * 256];
__device__ float g_scores[T256 * NCLS];
__device__ float g_lin[NROWS * D512];
__device__ float g_xin[NROWS * D512];
__device__ float g_hid[NROWS * MAXH];
__device__ float g_mlpout[NROWS * D512];
__device__ float g_z[NROWS * D512];
__device__ int   g_preE[NROWS];
__device__ int   g_mlpE[NROWS];
__device__ int   g_postE[NROWS];
__device__ float g_wgt[NROWS];
__device__ int   g_cnt[48];
__device__ int   g_cur[48];
__device__ int   g_off[51];
__device__ int   g_permP[NROWS];
__device__ int   g_permM[NROWS];
__device__ int   g_permQ[NROWS];

// ---------------- activations ----------------
__device__ __forceinline__ float act_apply(int a, float v) {
    switch (a & 3) {
        case 0:  return 0.5f * v * (1.0f + erff(v * 0.70710678118654752f));
        case 1:  return fmaxf(v, 0.0f);
        case 2:  return tanhf(v);
        default: return v * (1.0f / (1.0f + expf(-v)));
    }
}

__device__ __forceinline__ uint32_t to_tf32_u(float x) {
    uint32_t u;
    asm("cvt.rna.tf32.f32 %0, %1;" : "=r"(u) : "f"(x));
    return u;
}
__device__ __forceinline__ float round_tf32(float x) {
    return __uint_as_float(to_tf32_u(x));
}

__device__ __forceinline__ void mma_tf32(float c[4], const uint32_t a[4], const uint32_t b[2]) {
    asm volatile(
        "mma.sync.aligned.m16n8k8.row.col.f32.tf32.tf32.f32 "
        "{%0,%1,%2,%3}, {%4,%5,%6,%7}, {%8,%9}, {%0,%1,%2,%3};"
        : "+f"(c[0]), "+f"(c[1]), "+f"(c[2]), "+f"(c[3])
        : "r"(a[0]), "r"(a[1]), "r"(a[2]), "r"(a[3]), "r"(b[0]), "r"(b[1]));
}

__device__ __forceinline__ void cp16(uint32_t smem_addr, const void* gptr, bool valid) {
    int sz = valid ? 16 : 0;
    asm volatile("cp.async.ca.shared.global [%0], [%1], 16, %2;"
                 :: "r"(smem_addr), "l"(gptr), "r"(sz));
}
__device__ __forceinline__ void cp_commit() {
    asm volatile("cp.async.commit_group;");
}
template<int N>
__device__ __forceinline__ void cp_wait() {
    asm volatile("cp.async.wait_group %0;" :: "n"(N));
}

// ================= fp32 FFMA GEMM (router only: precision-critical) ========
#define BM 32
#define BN 128
#define BK 16

template<int ACT>
__global__ __launch_bounds__(256)
void gemm_k(const float* __restrict__ X, int ldx,
            const float* __restrict__ W, int ldw,
            const float* __restrict__ bias,
            float* __restrict__ Y, int ldy,
            int M, int K)
{
    int n0 = blockIdx.x * BN;
    int m0 = blockIdx.y * BM;
    if (m0 >= M) return;

    __shared__ float Xs[BK][BM];
    __shared__ float Ws[BK][BN];

    int tid = threadIdx.x;
    int tx = tid & 31, ty = tid >> 5;
    int c0 = tx * 4, r0 = ty * 4;

    float acc[4][4];
#pragma unroll
    for (int i = 0; i < 4; i++)
#pragma unroll
        for (int j = 0; j < 4; j++) acc[i][j] = 0.0f;

    int xm = tid >> 2, xk = (tid & 3) * 4;
    const float* xp = X + (long)(m0 + xm) * ldx;
    bool xok = (tid < 128) && (m0 + xm < M);

    for (int k0 = 0; k0 < K; k0 += BK) {
        const float* wp = W + (long)(k0 + ty) * ldw + n0 + c0;
        float4 w0 = *(const float4*)wp;
        float4 w1 = *(const float4*)(wp + (long)8 * ldw);
        float4 xv = make_float4(0.f, 0.f, 0.f, 0.f);
        if (xok) xv = *(const float4*)(xp + k0 + xk);

        *(float4*)&Ws[ty][c0]     = w0;
        *(float4*)&Ws[ty + 8][c0] = w1;
        if (tid < 128) {
            Xs[xk + 0][xm] = xv.x; Xs[xk + 1][xm] = xv.y;
            Xs[xk + 2][xm] = xv.z; Xs[xk + 3][xm] = xv.w;
        }
        __syncthreads();

#pragma unroll
        for (int kk = 0; kk < BK; kk++) {
            float4 a = *(const float4*)&Xs[kk][r0];
            float4 b = *(const float4*)&Ws[kk][c0];
            acc[0][0] += a.x * b.x; acc[0][1] += a.x * b.y; acc[0][2] += a.x * b.z; acc[0][3] += a.x * b.w;
            acc[1][0] += a.y * b.x; acc[1][1] += a.y * b.y; acc[1][2] += a.y * b.z; acc[1][3] += a.y * b.w;
            acc[2][0] += a.z * b.x; acc[2][1] += a.z * b.y; acc[2][2] += a.z * b.z; acc[2][3] += a.z * b.w;
            acc[3][0] += a.w * b.x; acc[3][1] += a.w * b.y; acc[3][2] += a.w * b.z; acc[3][3] += a.w * b.w;
        }
        __syncthreads();
    }

    float4 bb = *(const float4*)(bias + n0 + c0);
#pragma unroll
    for (int i = 0; i < 4; i++) {
        int r = m0 + r0 + i;
        if (r >= M) continue;
        float4 o;
        o.x = acc[i][0] + bb.x; o.y = acc[i][1] + bb.y;
        o.z = acc[i][2] + bb.z; o.w = acc[i][3] + bb.w;
        if (ACT == 1) {
            o.x = act_apply(0, o.x); o.y = act_apply(0, o.y);
            o.z = act_apply(0, o.z); o.w = act_apply(0, o.w);
        }
        *(float4*)(Y + (long)r * ldy + n0 + c0) = o;
    }
}

// ===== tf32 grouped GEMM: BM=64, BN=256, BK=16, warp tile 32x64 ============
// 8 warps (2m x 4n). 3-stage cp.async. A-side cvt removed when X is
// producer-rounded (XCVT=0); RND=1 rounds outputs to tf32 for the next GEMM.
#define STAGES 3
#define XPAD 20
#define WPAD 264
#define XS_SZ (64 * XPAD)
#define WS_SZ (16 * WPAD)
#define TC_SMEM_BYTES (STAGES * (XS_SZ + WS_SZ) * (int)sizeof(float) + 64 * (int)sizeof(int))

template<int ACT, int NKMODE, int XCVT, int RND>
__global__ __launch_bounds__(256)
void gemm_tc(const float* __restrict__ X, int ldx, int xshift,
             const float* __restrict__ W, long wstride, int ldw,
             const float* __restrict__ bias, int bstride,
             float* __restrict__ Y, int ldy,
             int K,
             const int* __restrict__ perm, const int* __restrict__ segoff)
{
    int e  = blockIdx.z;
    int n0 = blockIdx.x * 256;
    int he = 512 * (2 + (e >> 2));
    if (NKMODE == 1 && n0 >= he) return;
    int Keff = (NKMODE == 2) ? he : K;

    int segs = segoff[e], sege = segoff[e + 1];
    int m0 = segs + blockIdx.y * 64;
    if (m0 >= sege) return;

    extern __shared__ float sm[];
    float* XsB = sm;
    float* WsB = sm + STAGES * XS_SZ;
    int*   rows = (int*)(sm + STAGES * (XS_SZ + WS_SZ));

    int tid = threadIdx.x;
    if (tid < 64) {
        int p = m0 + tid;
        rows[tid] = (p < sege) ? perm[p] : -1;
    }
    __syncthreads();

    const float* Wb = W + (long)e * wstride;

    // X loader: 64x16 tile, 1 float4/thread
    int xrow = tid >> 2, xc4 = (tid & 3) * 4;
    int xr = rows[xrow];
    const float* xp = X + (long)((xr >= 0 ? xr : 0) >> xshift) * ldx;
    bool xok = (xr >= 0);

    // W loader: 16x256 tile, 4 float4/thread: chunk c = t*256+tid
    uint32_t xs_dst[STAGES], ws_dst[STAGES][4];
    int wr[4], wc[4];
#pragma unroll
    for (int t = 0; t < 4; t++) {
        int c = t * 256 + tid;
        wr[t] = c >> 6;
        wc[t] = (c & 63) * 4;
    }
#pragma unroll
    for (int s = 0; s < STAGES; s++) {
        xs_dst[s] = (uint32_t)__cvta_generic_to_shared(&XsB[s * XS_SZ + xrow * XPAD + xc4]);
#pragma unroll
        for (int t = 0; t < 4; t++)
            ws_dst[s][t] = (uint32_t)__cvta_generic_to_shared(&WsB[s * WS_SZ + wr[t] * WPAD + wc[t]]);
    }

    int nk = Keff >> 4;

    // prologue
#pragma unroll
    for (int s = 0; s < STAGES - 1; s++) {
        if (s < nk) {
            int k0 = s << 4;
#pragma unroll
            for (int t = 0; t < 4; t++)
                cp16(ws_dst[s][t], Wb + (long)(k0 + wr[t]) * ldw + n0 + wc[t], true);
            cp16(xs_dst[s], xp + k0 + xc4, xok);
        }
        cp_commit();
    }

    int lane = tid & 31, warp = tid >> 5;
    int wm = warp >> 2, wn = warp & 3;   // 2 x 4 warp grid; warp tile 32x64
    int lr = lane >> 2, lc = lane & 3;

    float c[2][8][4];
#pragma unroll
    for (int i = 0; i < 2; i++)
#pragma unroll
        for (int j = 0; j < 8; j++)
#pragma unroll
            for (int q = 0; q < 4; q++) c[i][j][q] = 0.0f;

    for (int t = 0; t < nk; t++) {
        cp_wait<STAGES - 2>();
        __syncthreads();

        int tn = t + STAGES - 1;
        if (tn < nk) {
            int k0 = tn << 4;
            int s = tn % STAGES;
#pragma unroll
            for (int u = 0; u < 4; u++)
                cp16(ws_dst[s][u], Wb + (long)(k0 + wr[u]) * ldw + n0 + wc[u], true);
            cp16(xs_dst[s], xp + k0 + xc4, xok);
        }
        cp_commit();

        int buf = t % STAGES;
        const float* Xb = XsB + buf * XS_SZ;
        const float* Wv = WsB + buf * WS_SZ;
#pragma unroll
        for (int ks = 0; ks < 16; ks += 8) {
            uint32_t a[2][4], b[8][2];
#pragma unroll
            for (int i = 0; i < 2; i++) {
                int bm = wm * 32 + i * 16;
                float a0 = Xb[(bm + lr    ) * XPAD + ks + lc    ];
                float a1 = Xb[(bm + lr + 8) * XPAD + ks + lc    ];
                float a2 = Xb[(bm + lr    ) * XPAD + ks + lc + 4];
                float a3 = Xb[(bm + lr + 8) * XPAD + ks + lc + 4];
                if (XCVT) {
                    a[i][0] = to_tf32_u(a0); a[i][1] = to_tf32_u(a1);
                    a[i][2] = to_tf32_u(a2); a[i][3] = to_tf32_u(a3);
                } else {
                    a[i][0] = __float_as_uint(a0); a[i][1] = __float_as_uint(a1);
                    a[i][2] = __float_as_uint(a2); a[i][3] = __float_as_uint(a3);
                }
            }
#pragma unroll
            for (int j = 0; j < 8; j++) {
                int bn = wn * 64 + j * 8 + lr;
                b[j][0] = to_tf32_u(Wv[(ks + lc    ) * WPAD + bn]);
                b[j][1] = to_tf32_u(Wv[(ks + lc + 4) * WPAD + bn]);
            }
#pragma unroll
            for (int i = 0; i < 2; i++)
#pragma unroll
                for (int j = 0; j < 8; j++)
                    mma_tf32(c[i][j], a[i], b[j]);
        }
    }

    // epilogue: bias + optional act (+ tf32 rounding when RND), scatter rows
#pragma unroll
    for (int j = 0; j < 8; j++) {
        int n = n0 + wn * 64 + j * 8 + 2 * lc;
        float2 bb = *(const float2*)(bias + (long)e * bstride + n);
#pragma unroll
        for (int i = 0; i < 2; i++) {
            int base = wm * 32 + i * 16 + lr;
            int ra = rows[base];
            int rb = rows[base + 8];
            if (ra >= 0) {
                float o0 = c[i][j][0] + bb.x, o1 = c[i][j][1] + bb.y;
                if (ACT == 2) { o0 = act_apply(e, o0); o1 = act_apply(e, o1); }
                if (RND) { o0 = round_tf32(o0); o1 = round_tf32(o1); }
                *(float2*)(Y + (long)ra * ldy + n) = make_float2(o0, o1);
            }
            if (rb >= 0) {
                float o0 = c[i][j][2] + bb.x, o1 = c[i][j][3] + bb.y;
                if (ACT == 2) { o0 = act_apply(e, o0); o1 = act_apply(e, o1); }
                if (RND) { o0 = round_tf32(o0); o1 = round_tf32(o1); }
                *(float2*)(Y + (long)rb * ldy + n) = make_float2(o0, o1);
            }
        }
    }
}

// ---------------- softmax + top-8 + route decompose ----------------
__global__ __launch_bounds__(256)
void topk_k(const float* __restrict__ scores, const float* __restrict__ temp,
            int* __restrict__ preE, int* __restrict__ mlpE, int* __restrict__ postE,
            float* __restrict__ wgt, int* __restrict__ cnt)
{
    int t = blockIdx.x;
    __shared__ float s[NCLS];
    __shared__ float rv[256];
    __shared__ int   ri[256];
    __shared__ float selv[TOPK];
    __shared__ int   seli[TOPK];

    int tid = threadIdx.x;
    float invT = 1.0f / temp[0];
    for (int i = tid; i < NCLS; i += 256) s[i] = scores[(long)t * NCLS + i] * invT;
    __syncthreads();

    float m = -INFINITY;
    for (int i = tid; i < NCLS; i += 256) m = fmaxf(m, s[i]);
    rv[tid] = m; __syncthreads();
    for (int o = 128; o > 0; o >>= 1) { if (tid < o) rv[tid] = fmaxf(rv[tid], rv[tid + o]); __syncthreads(); }
    m = rv[0]; __syncthreads();

    float sum = 0.0f;
    for (int i = tid; i < NCLS; i += 256) sum += expf(s[i] - m);
    rv[tid] = sum; __syncthreads();
    for (int o = 128; o > 0; o >>= 1) { if (tid < o) rv[tid] += rv[tid + o]; __syncthreads(); }
    float denom = rv[0]; __syncthreads();

    for (int it = 0; it < TOPK; it++) {
        float bv = -INFINITY; int bi = -1;
        for (int i = tid; i < NCLS; i += 256) {
            bool used = false;
            for (int j = 0; j < it; j++) if (seli[j] == i) used = true;
            if (!used) {
                float v = s[i];
                if (v > bv || (v == bv && (unsigned)i < (unsigned)bi)) { bv = v; bi = i; }
            }
        }
        rv[tid] = bv; ri[tid] = bi; __syncthreads();
        for (int o = 128; o > 0; o >>= 1) {
            if (tid < o) {
                if (rv[tid + o] > rv[tid] ||
                    (rv[tid + o] == rv[tid] && (unsigned)ri[tid + o] < (unsigned)ri[tid])) {
                    rv[tid] = rv[tid + o]; ri[tid] = ri[tid + o];
                }
            }
            __syncthreads();
        }
        if (tid == 0) { selv[it] = rv[0]; seli[it] = ri[0]; }
        __syncthreads();
    }

    if (tid < TOPK) {
        int idx = seli[tid];
        float p = expf(selv[tid] - m) / denom;
        float w = (p >= 1e-6f) ? p : 0.0f;
        int pe = idx >> 8;
        int rem = idx & 255;
        int me = rem >> 4;
        int qe = rem & 15;
        int r = t * TOPK + tid;
        preE[r] = pe; mlpE[r] = me; postE[r] = qe; wgt[r] = w;
        atomicAdd(&cnt[pe], 1);
        atomicAdd(&cnt[16 + me], 1);
        atomicAdd(&cnt[32 + qe], 1);
    }
}

__global__ void zero_k(int* cnt, int* cur) {
    int i = threadIdx.x;
    if (i < 48) { cnt[i] = 0; cur[i] = 0; }
}

__global__ void scan_k(const int* __restrict__ cnt, int* __restrict__ off) {
    if (threadIdx.x == 0) {
        for (int gp = 0; gp < 3; gp++) {
            int a = 0;
            for (int i = 0; i < 16; i++) { off[gp * 17 + i] = a; a += cnt[gp * 16 + i]; }
            off[gp * 17 + 16] = a;
        }
    }
}

__global__ void scatter_k(const int* __restrict__ preE, const int* __restrict__ mlpE,
                          const int* __restrict__ postE, const int* __restrict__ off,
                          int* __restrict__ cur,
                          int* __restrict__ permP, int* __restrict__ permM, int* __restrict__ permQ)
{
    int i = blockIdx.x * blockDim.x + threadIdx.x;
    if (i >= NROWS) return;
    int e, p;
    e = preE[i];  p = off[e]       + atomicAdd(&cur[e],      1); permP[p] = i;
    e = mlpE[i];  p = off[17 + e]  + atomicAdd(&cur[16 + e], 1); permM[p] = i;
    e = postE[i]; p = off[34 + e]  + atomicAdd(&cur[32 + e], 1); permQ[p] = i;
}

// ---------------- row layernorm (+optional act) ----------------
// MODE 0: pre (LN + act, output tf32-rounded for the mlp1 GEMM).
// MODE 1: post (LN only if e even; feeds final combine, NOT rounded).
template<int MODE>
__global__ __launch_bounds__(256)
void ln_k(const float* __restrict__ in, float* __restrict__ out,
          const int* __restrict__ eArr, const float* __restrict__ g, const float* __restrict__ be)
{
    int row = blockIdx.x;
    int e = eArr[row];
    const float* xp = in + (long)row * D512;
    float* yp = out + (long)row * D512;
    int tid = threadIdx.x;
    float v0 = xp[tid], v1 = xp[tid + 256];
    if (MODE == 1 && (e & 1)) { yp[tid] = v0; yp[tid + 256] = v1; return; }

    __shared__ float red[256];
    red[tid] = v0 + v1; __syncthreads();
    for (int o = 128; o > 0; o >>= 1) { if (tid < o) red[tid] += red[tid + o]; __syncthreads(); }
    float mu = red[0] * (1.0f / 512.0f);
    __syncthreads();
    float d0 = v0 - mu, d1 = v1 - mu;
    red[tid] = d0 * d0 + d1 * d1; __syncthreads();
    for (int o = 128; o > 0; o >>= 1) { if (tid < o) red[tid] += red[tid + o]; __syncthreads(); }
    float rstd = rsqrtf(red[0] * (1.0f / 512.0f) + 1e-5f);

    float y0 = d0 * rstd * g[e * D512 + tid]       + be[e * D512 + tid];
    float y1 = d1 * rstd * g[e * D512 + tid + 256] + be[e * D512 + tid + 256];
    if (MODE == 0) {
        y0 = round_tf32(act_apply(e, y0));
        y1 = round_tf32(act_apply(e, y1));
    }
    yp[tid] = y0; yp[tid + 256] = y1;
}

// ---------------- weighted combine ----------------
__global__ void final_k(const float* __restrict__ z, const float* __restrict__ wgt,
                        float* __restrict__ out)
{
    int t = blockIdx.x, d = threadIdx.x;
    float acc = 0.0f;
#pragma unroll
    for (int k = 0; k < TOPK; k++) {
        int r = t * TOPK + k;
        acc += wgt[r] * z[(long)r * D512 + d];
    }
    out[(long)t * D512 + d] = acc;
}

// ---------------- launch ----------------
template <typename Tv>
static float* symf(Tv& v) { void* p = nullptr; cudaGetSymbolAddress(&p, v); return (float*)p; }
template <typename Tv>
static int* symi(Tv& v) { void* p = nullptr; cudaGetSymbolAddress(&p, v); return (int*)p; }

extern "C" void kernel_launch(void* const* d_in, const int* in_sizes, int n_in,
                              void* d_out, int out_size)
{
    const float* x      = (const float*)d_in[0];
    const float* r_w1   = (const float*)d_in[1];
    const float* r_b1   = (const float*)d_in[2];
    const float* r_w2   = (const float*)d_in[3];
    const float* r_b2   = (const float*)d_in[4];
    const float* r_w3   = (const float*)d_in[5];
    const float* r_b3   = (const float*)d_in[6];
    const float* temp   = (const float*)d_in[7];
    const float* pre_w  = (const float*)d_in[8];
    const float* pre_b  = (const float*)d_in[9];
    const float* pre_g  = (const float*)d_in[10];
    const float* pre_be = (const float*)d_in[11];
    const float* mlp_w1 = (const float*)d_in[12];
    const float* mlp_b1 = (const float*)d_in[13];
    const float* mlp_w2 = (const float*)d_in[14];
    const float* mlp_b2 = (const float*)d_in[15];
    const float* post_w = (const float*)d_in[16];
    const float* post_b = (const float*)d_in[17];
    const float* post_g = (const float*)d_in[18];
    const float* post_be= (const float*)d_in[19];
    float* out = (float*)d_out;

    float* h1     = symf(g_h1);
    float* h2     = symf(g_h2);
    float* scores = symf(g_scores);
    float* lin    = symf(g_lin);
    float* xin    = symf(g_xin);
    float* hid    = symf(g_hid);
    float* mout   = symf(g_mlpout);
    float* zbuf   = symf(g_z);
    float* wgt    = symf(g_wgt);
    int* preE  = symi(g_preE);
    int* mlpE  = symi(g_mlpE);
    int* postE = symi(g_postE);
    int* cnt   = symi(g_cnt);
    int* cur   = symi(g_cur);
    int* off   = symi(g_off);
    int* permP = symi(g_permP);
    int* permM = symi(g_permM);
    int* permQ = symi(g_permQ);

    cudaFuncSetAttribute(gemm_tc<0, 0, 1, 0>, cudaFuncAttributeMaxDynamicSharedMemorySize, TC_SMEM_BYTES);
    cudaFuncSetAttribute(gemm_tc<2, 1, 0, 1>, cudaFuncAttributeMaxDynamicSharedMemorySize, TC_SMEM_BYTES);
    cudaFuncSetAttribute(gemm_tc<0, 2, 0, 1>, cudaFuncAttributeMaxDynamicSharedMemorySize, TC_SMEM_BYTES);
    cudaFuncSetAttribute(gemm_tc<0, 0, 0, 0>, cudaFuncAttributeMaxDynamicSharedMemorySize, TC_SMEM_BYTES);

    // zero first (no deps) — keeps the scores GEMM in the ncu capture slot.
    zero_k<<<1, 64>>>(cnt, cur);

    // router (fp32 — top-k selection is precision-critical)
    gemm_k<1><<<dim3(4, 8, 1), 256>>>(x, 512, r_w1, 512, r_b1, h1, 512, 256, 512);
    gemm_k<1><<<dim3(2, 8, 1), 256>>>(h1, 512, r_w2, 256, r_b2, h2, 256, 256, 512);
    gemm_k<0><<<dim3(32, 8, 1), 256>>>(h2, 256, r_w3, 4096, r_b3, scores, 4096, 256, 256);

    // routing
    topk_k<<<256, 256>>>(scores, temp, preE, mlpE, postE, wgt, cnt);
    scan_k<<<1, 32>>>(cnt, off);
    scatter_k<<<8, 256>>>(preE, mlpE, postE, off, cur, permP, permM, permQ);

    // pre experts (X = raw x -> XCVT=1; output feeds LN, not rounded)
    gemm_tc<0, 0, 1, 0><<<dim3(2, 32, 16), 256, TC_SMEM_BYTES>>>(
        x, 512, 3, pre_w, 512L * 512, 512, pre_b, 512, lin, 512, 512, permP, off);
    ln_k<0><<<2048, 256>>>(lin, xin, preE, pre_g, pre_be);   // rounds xin

    // mlp experts (inputs pre-rounded -> XCVT=0; outputs feed GEMMs -> RND=1)
    gemm_tc<2, 1, 0, 1><<<dim3(10, 32, 16), 256, TC_SMEM_BYTES>>>(
        xin, 512, 0, mlp_w1, 512L * 2560, 2560, mlp_b1, 2560, hid, 2560, 512, permM, off + 17);
    gemm_tc<0, 2, 0, 1><<<dim3(2, 32, 16), 256, TC_SMEM_BYTES>>>(
        hid, 2560, 0, mlp_w2, 2560L * 512, 512, mlp_b2, 512, mout, 512, 0, permM, off + 17);

    // post experts (input mout pre-rounded -> XCVT=0; output feeds LN/final)
    gemm_tc<0, 0, 0, 0><<<dim3(2, 32, 16), 256, TC_SMEM_BYTES>>>(
        mout, 512, 0, post_w, 512L * 512, 512, post_b, 512, lin, 512, 512, permQ, off + 34);
    ln_k<1><<<2048, 256>>>(lin, zbuf, postE, post_g, post_be);

    // weighted combine
    final_k<<<256, 512>>>(zbuf, wgt, out);
    (void)in_sizes; (void)n_in; (void)out_size;
}

// round 13
// speedup vs baseline: 1.5670x; 1.3007x over previous
#include <cuda_runtime.h>
#include <cuda_bf16.h>
#include <math.h>
#include <stdint.h>

// Problem constants
#define D512 512
#define T256 256
#define NROWS 2048          // T * TOPK
#define MAXH 2560
#define NEXP 16
#define NCLS 4096
#define TOPK 8
#define MAXCH 5             // max K-chunks for mlp2 split-K (he/512 <= 5)

// ---------------- scratch (device globals; no allocation allowed) ----------
__device__ float g_h1[T256 * D512];
__device__ float g_h2[T256 * 256];
__device__ float g_scores[T256 * NCLS];
__device__ float g_lin[NROWS * D512];
__device__ float g_xin[NROWS * D512];
__device__ float g_hid[NROWS * MAXH];
__device__ float g_mlpout[NROWS * D512];
__device__ float g_z[NROWS * D512];
__device__ float g_part[MAXCH * NROWS * D512];   // split-K partials (20MB)
__device__ int   g_preE[NROWS];
__device__ int   g_mlpE[NROWS];
__device__ int   g_postE[NROWS];
__device__ float g_wgt[NROWS];
__device__ int   g_cnt[48];
__device__ int   g_cur[48];
__device__ int   g_off[51];
__device__ int   g_permP[NROWS];
__device__ int   g_permM[NROWS];
__device__ int   g_permQ[NROWS];

// ---------------- activations ----------------
__device__ __forceinline__ float act_apply(int a, float v) {
    switch (a & 3) {
        case 0:  return 0.5f * v * (1.0f + erff(v * 0.70710678118654752f));
        case 1:  return fmaxf(v, 0.0f);
        case 2:  return tanhf(v);
        default: return v * (1.0f / (1.0f + expf(-v)));
    }
}

__device__ __forceinline__ uint32_t to_tf32_u(float x) {
    uint32_t u;
    asm("cvt.rna.tf32.f32 %0, %1;" : "=r"(u) : "f"(x));
    return u;
}
__device__ __forceinline__ float round_tf32(float x) {
    return __uint_as_float(to_tf32_u(x));
}

__device__ __forceinline__ void mma_tf32(float c[4], const uint32_t a[4], const uint32_t b[2]) {
    asm volatile(
        "mma.sync.aligned.m16n8k8.row.col.f32.tf32.tf32.f32 "
        "{%0,%1,%2,%3}, {%4,%5,%6,%7}, {%8,%9}, {%0,%1,%2,%3};"
        : "+f"(c[0]), "+f"(c[1]), "+f"(c[2]), "+f"(c[3])
        : "r"(a[0]), "r"(a[1]), "r"(a[2]), "r"(a[3]), "r"(b[0]), "r"(b[1]));
}

__device__ __forceinline__ void cp16(uint32_t smem_addr, const void* gptr, bool valid) {
    int sz = valid ? 16 : 0;
    asm volatile("cp.async.ca.shared.global [%0], [%1], 16, %2;"
                 :: "r"(smem_addr), "l"(gptr), "r"(sz));
}
__device__ __forceinline__ void cp_commit() {
    asm volatile("cp.async.commit_group;");
}
template<int N>
__device__ __forceinline__ void cp_wait() {
    asm volatile("cp.async.wait_group %0;" :: "n"(N));
}

// ================= fp32 FFMA GEMM (router only: precision-critical) ========
#define BM 32
#define BN 128
#define BK 16

template<int ACT>
__global__ __launch_bounds__(256)
void gemm_k(const float* __restrict__ X, int ldx,
            const float* __restrict__ W, int ldw,
            const float* __restrict__ bias,
            float* __restrict__ Y, int ldy,
            int M, int K)
{
    int n0 = blockIdx.x * BN;
    int m0 = blockIdx.y * BM;
    if (m0 >= M) return;

    __shared__ float Xs[BK][BM];
    __shared__ float Ws[BK][BN];

    int tid = threadIdx.x;
    int tx = tid & 31, ty = tid >> 5;
    int c0 = tx * 4, r0 = ty * 4;

    float acc[4][4];
#pragma unroll
    for (int i = 0; i < 4; i++)
#pragma unroll
        for (int j = 0; j < 4; j++) acc[i][j] = 0.0f;

    int xm = tid >> 2, xk = (tid & 3) * 4;
    const float* xp = X + (long)(m0 + xm) * ldx;
    bool xok = (tid < 128) && (m0 + xm < M);

    for (int k0 = 0; k0 < K; k0 += BK) {
        const float* wp = W + (long)(k0 + ty) * ldw + n0 + c0;
        float4 w0 = *(const float4*)wp;
        float4 w1 = *(const float4*)(wp + (long)8 * ldw);
        float4 xv = make_float4(0.f, 0.f, 0.f, 0.f);
        if (xok) xv = *(const float4*)(xp + k0 + xk);

        *(float4*)&Ws[ty][c0]     = w0;
        *(float4*)&Ws[ty + 8][c0] = w1;
        if (tid < 128) {
            Xs[xk + 0][xm] = xv.x; Xs[xk + 1][xm] = xv.y;
            Xs[xk + 2][xm] = xv.z; Xs[xk + 3][xm] = xv.w;
        }
        __syncthreads();

#pragma unroll
        for (int kk = 0; kk < BK; kk++) {
            float4 a = *(const float4*)&Xs[kk][r0];
            float4 b = *(const float4*)&Ws[kk][c0];
            acc[0][0] += a.x * b.x; acc[0][1] += a.x * b.y; acc[0][2] += a.x * b.z; acc[0][3] += a.x * b.w;
            acc[1][0] += a.y * b.x; acc[1][1] += a.y * b.y; acc[1][2] += a.y * b.z; acc[1][3] += a.y * b.w;
            acc[2][0] += a.z * b.x; acc[2][1] += a.z * b.y; acc[2][2] += a.z * b.z; acc[2][3] += a.z * b.w;
            acc[3][0] += a.w * b.x; acc[3][1] += a.w * b.y; acc[3][2] += a.w * b.z; acc[3][3] += a.w * b.w;
        }
        __syncthreads();
    }

    float4 bb = *(const float4*)(bias + n0 + c0);
#pragma unroll
    for (int i = 0; i < 4; i++) {
        int r = m0 + r0 + i;
        if (r >= M) continue;
        float4 o;
        o.x = acc[i][0] + bb.x; o.y = acc[i][1] + bb.y;
        o.z = acc[i][2] + bb.z; o.w = acc[i][3] + bb.w;
        if (ACT == 1) {
            o.x = act_apply(0, o.x); o.y = act_apply(0, o.y);
            o.z = act_apply(0, o.z); o.w = act_apply(0, o.w);
        }
        *(float4*)(Y + (long)r * ldy + n0 + c0) = o;
    }
}

// ===== tf32 grouped GEMM: BM=64, BN=256, BK=16, warp tile 32x64 ============
#define STAGES 3
#define XPAD 20
#define WPAD 264
#define XS_SZ (64 * XPAD)
#define WS_SZ (16 * WPAD)
#define TC_SMEM_BYTES (STAGES * (XS_SZ + WS_SZ) * (int)sizeof(float) + 64 * (int)sizeof(int))

template<int ACT, int NKMODE, int XCVT, int RND>
__global__ __launch_bounds__(256)
void gemm_tc(const float* __restrict__ X, int ldx, int xshift,
             const float* __restrict__ W, long wstride, int ldw,
             const float* __restrict__ bias, int bstride,
             float* __restrict__ Y, int ldy,
             int K,
             const int* __restrict__ perm, const int* __restrict__ segoff)
{
    int e  = blockIdx.z;
    int n0 = blockIdx.x * 256;
    int he = 512 * (2 + (e >> 2));
    if (NKMODE == 1 && n0 >= he) return;
    int Keff = (NKMODE == 2) ? he : K;

    int segs = segoff[e], sege = segoff[e + 1];
    int m0 = segs + blockIdx.y * 64;
    if (m0 >= sege) return;

    extern __shared__ float sm[];
    float* XsB = sm;
    float* WsB = sm + STAGES * XS_SZ;
    int*   rows = (int*)(sm + STAGES * (XS_SZ + WS_SZ));

    int tid = threadIdx.x;
    if (tid < 64) {
        int p = m0 + tid;
        rows[tid] = (p < sege) ? perm[p] : -1;
    }
    __syncthreads();

    const float* Wb = W + (long)e * wstride;

    int xrow = tid >> 2, xc4 = (tid & 3) * 4;
    int xr = rows[xrow];
    const float* xp = X + (long)((xr >= 0 ? xr : 0) >> xshift) * ldx;
    bool xok = (xr >= 0);

    uint32_t xs_dst[STAGES], ws_dst[STAGES][4];
    int wr[4], wc[4];
#pragma unroll
    for (int t = 0; t < 4; t++) {
        int c = t * 256 + tid;
        wr[t] = c >> 6;
        wc[t] = (c & 63) * 4;
    }
#pragma unroll
    for (int s = 0; s < STAGES; s++) {
        xs_dst[s] = (uint32_t)__cvta_generic_to_shared(&XsB[s * XS_SZ + xrow * XPAD + xc4]);
#pragma unroll
        for (int t = 0; t < 4; t++)
            ws_dst[s][t] = (uint32_t)__cvta_generic_to_shared(&WsB[s * WS_SZ + wr[t] * WPAD + wc[t]]);
    }

    int nk = Keff >> 4;

#pragma unroll
    for (int s = 0; s < STAGES - 1; s++) {
        if (s < nk) {
            int k0 = s << 4;
#pragma unroll
            for (int t = 0; t < 4; t++)
                cp16(ws_dst[s][t], Wb + (long)(k0 + wr[t]) * ldw + n0 + wc[t], true);
            cp16(xs_dst[s], xp + k0 + xc4, xok);
        }
        cp_commit();
    }

    int lane = tid & 31, warp = tid >> 5;
    int wm = warp >> 2, wn = warp & 3;
    int lr = lane >> 2, lc = lane & 3;

    float c[2][8][4];
#pragma unroll
    for (int i = 0; i < 2; i++)
#pragma unroll
        for (int j = 0; j < 8; j++)
#pragma unroll
            for (int q = 0; q < 4; q++) c[i][j][q] = 0.0f;

    for (int t = 0; t < nk; t++) {
        cp_wait<STAGES - 2>();
        __syncthreads();

        int tn = t + STAGES - 1;
        if (tn < nk) {
            int k0 = tn << 4;
            int s = tn % STAGES;
#pragma unroll
            for (int u = 0; u < 4; u++)
                cp16(ws_dst[s][u], Wb + (long)(k0 + wr[u]) * ldw + n0 + wc[u], true);
            cp16(xs_dst[s], xp + k0 + xc4, xok);
        }
        cp_commit();

        int buf = t % STAGES;
        const float* Xb = XsB + buf * XS_SZ;
        const float* Wv = WsB + buf * WS_SZ;
#pragma unroll
        for (int ks = 0; ks < 16; ks += 8) {
            uint32_t a[2][4], b[8][2];
#pragma unroll
            for (int i = 0; i < 2; i++) {
                int bm = wm * 32 + i * 16;
                float a0 = Xb[(bm + lr    ) * XPAD + ks + lc    ];
                float a1 = Xb[(bm + lr + 8) * XPAD + ks + lc    ];
                float a2 = Xb[(bm + lr    ) * XPAD + ks + lc + 4];
                float a3 = Xb[(bm + lr + 8) * XPAD + ks + lc + 4];
                if (XCVT) {
                    a[i][0] = to_tf32_u(a0); a[i][1] = to_tf32_u(a1);
                    a[i][2] = to_tf32_u(a2); a[i][3] = to_tf32_u(a3);
                } else {
                    a[i][0] = __float_as_uint(a0); a[i][1] = __float_as_uint(a1);
                    a[i][2] = __float_as_uint(a2); a[i][3] = __float_as_uint(a3);
                }
            }
#pragma unroll
            for (int j = 0; j < 8; j++) {
                int bn = wn * 64 + j * 8 + lr;
                b[j][0] = to_tf32_u(Wv[(ks + lc    ) * WPAD + bn]);
                b[j][1] = to_tf32_u(Wv[(ks + lc + 4) * WPAD + bn]);
            }
#pragma unroll
            for (int i = 0; i < 2; i++)
#pragma unroll
                for (int j = 0; j < 8; j++)
                    mma_tf32(c[i][j], a[i], b[j]);
        }
    }

#pragma unroll
    for (int j = 0; j < 8; j++) {
        int n = n0 + wn * 64 + j * 8 + 2 * lc;
        float2 bb = *(const float2*)(bias + (long)e * bstride + n);
#pragma unroll
        for (int i = 0; i < 2; i++) {
            int base = wm * 32 + i * 16 + lr;
            int ra = rows[base];
            int rb = rows[base + 8];
            if (ra >= 0) {
                float o0 = c[i][j][0] + bb.x, o1 = c[i][j][1] + bb.y;
                if (ACT == 2) { o0 = act_apply(e, o0); o1 = act_apply(e, o1); }
                if (RND) { o0 = round_tf32(o0); o1 = round_tf32(o1); }
                *(float2*)(Y + (long)ra * ldy + n) = make_float2(o0, o1);
            }
            if (rb >= 0) {
                float o0 = c[i][j][2] + bb.x, o1 = c[i][j][3] + bb.y;
                if (ACT == 2) { o0 = act_apply(e, o0); o1 = act_apply(e, o1); }
                if (RND) { o0 = round_tf32(o0); o1 = round_tf32(o1); }
                *(float2*)(Y + (long)rb * ldy + n) = make_float2(o0, o1);
            }
        }
    }
}

// ===== split-K variant for mlp2: K chunked in 512s, raw partials out =======
// blockIdx.y = mtile*MAXCH + chunk. No bias/act/rnd (done in reduce_k).
__global__ __launch_bounds__(256)
void gemm_tc_sk(const float* __restrict__ X, int ldx,
                const float* __restrict__ W, long wstride, int ldw,
                float* __restrict__ Ypart,
                const int* __restrict__ perm, const int* __restrict__ segoff)
{
    int e  = blockIdx.z;
    int n0 = blockIdx.x * 256;
    int he = 512 * (2 + (e >> 2));
    int mtile = blockIdx.y / MAXCH;
    int chunk = blockIdx.y % MAXCH;
    int kstart = chunk * 512;
    if (kstart >= he) return;

    int segs = segoff[e], sege = segoff[e + 1];
    int m0 = segs + mtile * 64;
    if (m0 >= sege) return;

    extern __shared__ float sm[];
    float* XsB = sm;
    float* WsB = sm + STAGES * XS_SZ;
    int*   rows = (int*)(sm + STAGES * (XS_SZ + WS_SZ));

    int tid = threadIdx.x;
    if (tid < 64) {
        int p = m0 + tid;
        rows[tid] = (p < sege) ? perm[p] : -1;
    }
    __syncthreads();

    const float* Wb = W + (long)e * wstride;

    int xrow = tid >> 2, xc4 = (tid & 3) * 4;
    int xr = rows[xrow];
    const float* xp = X + (long)(xr >= 0 ? xr : 0) * ldx + kstart;
    bool xok = (xr >= 0);

    uint32_t xs_dst[STAGES], ws_dst[STAGES][4];
    int wr[4], wc[4];
#pragma unroll
    for (int t = 0; t < 4; t++) {
        int c = t * 256 + tid;
        wr[t] = c >> 6;
        wc[t] = (c & 63) * 4;
    }
#pragma unroll
    for (int s = 0; s < STAGES; s++) {
        xs_dst[s] = (uint32_t)__cvta_generic_to_shared(&XsB[s * XS_SZ + xrow * XPAD + xc4]);
#pragma unroll
        for (int t = 0; t < 4; t++)
            ws_dst[s][t] = (uint32_t)__cvta_generic_to_shared(&WsB[s * WS_SZ + wr[t] * WPAD + wc[t]]);
    }

    const int nk = 32;  // 512 / 16

#pragma unroll
    for (int s = 0; s < STAGES - 1; s++) {
        int k0 = s << 4;
#pragma unroll
        for (int t = 0; t < 4; t++)
            cp16(ws_dst[s][t], Wb + (long)(kstart + k0 + wr[t]) * ldw + n0 + wc[t], true);
        cp16(xs_dst[s], xp + k0 + xc4, xok);
        cp_commit();
    }

    int lane = tid & 31, warp = tid >> 5;
    int wm = warp >> 2, wn = warp & 3;
    int lr = lane >> 2, lc = lane & 3;

    float c[2][8][4];
#pragma unroll
    for (int i = 0; i < 2; i++)
#pragma unroll
        for (int j = 0; j < 8; j++)
#pragma unroll
            for (int q = 0; q < 4; q++) c[i][j][q] = 0.0f;

    for (int t = 0; t < nk; t++) {
        cp_wait<STAGES - 2>();
        __syncthreads();

        int tn = t + STAGES - 1;
        if (tn < nk) {
            int k0 = tn << 4;
            int s = tn % STAGES;
#pragma unroll
            for (int u = 0; u < 4; u++)
                cp16(ws_dst[s][u], Wb + (long)(kstart + k0 + wr[u]) * ldw + n0 + wc[u], true);
            cp16(xs_dst[s], xp + k0 + xc4, xok);
        }
        cp_commit();

        int buf = t % STAGES;
        const float* Xb = XsB + buf * XS_SZ;
        const float* Wv = WsB + buf * WS_SZ;
#pragma unroll
        for (int ks = 0; ks < 16; ks += 8) {
            uint32_t a[2][4], b[8][2];
#pragma unroll
            for (int i = 0; i < 2; i++) {
                int bm = wm * 32 + i * 16;
                a[i][0] = __float_as_uint(Xb[(bm + lr    ) * XPAD + ks + lc    ]);
                a[i][1] = __float_as_uint(Xb[(bm + lr + 8) * XPAD + ks + lc    ]);
                a[i][2] = __float_as_uint(Xb[(bm + lr    ) * XPAD + ks + lc + 4]);
                a[i][3] = __float_as_uint(Xb[(bm + lr + 8) * XPAD + ks + lc + 4]);
            }
#pragma unroll
            for (int j = 0; j < 8; j++) {
                int bn = wn * 64 + j * 8 + lr;
                b[j][0] = to_tf32_u(Wv[(ks + lc    ) * WPAD + bn]);
                b[j][1] = to_tf32_u(Wv[(ks + lc + 4) * WPAD + bn]);
            }
#pragma unroll
            for (int i = 0; i < 2; i++)
#pragma unroll
                for (int j = 0; j < 8; j++)
                    mma_tf32(c[i][j], a[i], b[j]);
        }
    }

    float* Yp = Ypart + (long)chunk * NROWS * D512;
#pragma unroll
    for (int j = 0; j < 8; j++) {
        int n = n0 + wn * 64 + j * 8 + 2 * lc;
#pragma unroll
        for (int i = 0; i < 2; i++) {
            int base = wm * 32 + i * 16 + lr;
            int ra = rows[base];
            int rb = rows[base + 8];
            if (ra >= 0)
                *(float2*)(Yp + (long)ra * D512 + n) = make_float2(c[i][j][0], c[i][j][1]);
            if (rb >= 0)
                *(float2*)(Yp + (long)rb * D512 + n) = make_float2(c[i][j][2], c[i][j][3]);
        }
    }
}

// fixed-order chunk reduction + bias + tf32 rounding -> mout
__global__ __launch_bounds__(256)
void reduce_k(const float* __restrict__ part, const int* __restrict__ mlpE,
              const float* __restrict__ bias, float* __restrict__ out)
{
    int row = blockIdx.x;
    int e = mlpE[row];
    int nch = 2 + (e >> 2);      // he/512
    int tid = threadIdx.x;
#pragma unroll
    for (int h = 0; h < 2; h++) {
        int n = tid + h * 256;
        float s = bias[(long)e * D512 + n];
        for (int c = 0; c < nch; c++)
            s += part[(long)c * NROWS * D512 + (long)row * D512 + n];
        out[(long)row * D512 + n] = round_tf32(s);
    }
}

// ---------------- softmax + top-8 + route decompose ----------------
__global__ __launch_bounds__(256)
void topk_k(const float* __restrict__ scores, const float* __restrict__ temp,
            int* __restrict__ preE, int* __restrict__ mlpE, int* __restrict__ postE,
            float* __restrict__ wgt, int* __restrict__ cnt)
{
    int t = blockIdx.x;
    __shared__ float s[NCLS];
    __shared__ float rv[256];
    __shared__ int   ri[256];
    __shared__ float selv[TOPK];
    __shared__ int   seli[TOPK];

    int tid = threadIdx.x;
    float invT = 1.0f / temp[0];
    for (int i = tid; i < NCLS; i += 256) s[i] = scores[(long)t * NCLS + i] * invT;
    __syncthreads();

    float m = -INFINITY;
    for (int i = tid; i < NCLS; i += 256) m = fmaxf(m, s[i]);
    rv[tid] = m; __syncthreads();
    for (int o = 128; o > 0; o >>= 1) { if (tid < o) rv[tid] = fmaxf(rv[tid], rv[tid + o]); __syncthreads(); }
    m = rv[0]; __syncthreads();

    float sum = 0.0f;
    for (int i = tid; i < NCLS; i += 256) sum += expf(s[i] - m);
    rv[tid] = sum; __syncthreads();
    for (int o = 128; o > 0; o >>= 1) { if (tid < o) rv[tid] += rv[tid + o]; __syncthreads(); }
    float denom = rv[0]; __syncthreads();

    for (int it = 0; it < TOPK; it++) {
        float bv = -INFINITY; int bi = -1;
        for (int i = tid; i < NCLS; i += 256) {
            bool used = false;
            for (int j = 0; j < it; j++) if (seli[j] == i) used = true;
            if (!used) {
                float v = s[i];
                if (v > bv || (v == bv && (unsigned)i < (unsigned)bi)) { bv = v; bi = i; }
            }
        }
        rv[tid] = bv; ri[tid] = bi; __syncthreads();
        for (int o = 128; o > 0; o >>= 1) {
            if (tid < o) {
                if (rv[tid + o] > rv[tid] ||
                    (rv[tid + o] == rv[tid] && (unsigned)ri[tid + o] < (unsigned)ri[tid])) {
                    rv[tid] = rv[tid + o]; ri[tid] = ri[tid + o];
                }
            }
            __syncthreads();
        }
        if (tid == 0) { selv[it] = rv[0]; seli[it] = ri[0]; }
        __syncthreads();
    }

    if (tid < TOPK) {
        int idx = seli[tid];
        float p = expf(selv[tid] - m) / denom;
        float w = (p >= 1e-6f) ? p : 0.0f;
        int pe = idx >> 8;
        int rem = idx & 255;
        int me = rem >> 4;
        int qe = rem & 15;
        int r = t * TOPK + tid;
        preE[r] = pe; mlpE[r] = me; postE[r] = qe; wgt[r] = w;
        atomicAdd(&cnt[pe], 1);
        atomicAdd(&cnt[16 + me], 1);
        atomicAdd(&cnt[32 + qe], 1);
    }
}

__global__ void zero_k(int* cnt, int* cur) {
    int i = threadIdx.x;
    if (i < 48) { cnt[i] = 0; cur[i] = 0; }
}

__global__ void scan_k(const int* __restrict__ cnt, int* __restrict__ off) {
    if (threadIdx.x == 0) {
        for (int gp = 0; gp < 3; gp++) {
            int a = 0;
            for (int i = 0; i < 16; i++) { off[gp * 17 + i] = a; a += cnt[gp * 16 + i]; }
            off[gp * 17 + 16] = a;
        }
    }
}

__global__ void scatter_k(const int* __restrict__ preE, const int* __restrict__ mlpE,
                          const int* __restrict__ postE, const int* __restrict__ off,
                          int* __restrict__ cur,
                          int* __restrict__ permP, int* __restrict__ permM, int* __restrict__ permQ)
{
    int i = blockIdx.x * blockDim.x + threadIdx.x;
    if (i >= NROWS) return;
    int e, p;
    e = preE[i];  p = off[e]       + atomicAdd(&cur[e],      1); permP[p] = i;
    e = mlpE[i];  p = off[17 + e]  + atomicAdd(&cur[16 + e], 1); permM[p] = i;
    e = postE[i]; p = off[34 + e]  + atomicAdd(&cur[32 + e], 1); permQ[p] = i;
}

// ---------------- row layernorm (+optional act) ----------------
template<int MODE>
__global__ __launch_bounds__(256)
void ln_k(const float* __restrict__ in, float* __restrict__ out,
          const int* __restrict__ eArr, const float* __restrict__ g, const float* __restrict__ be)
{
    int row = blockIdx.x;
    int e = eArr[row];
    const float* xp = in + (long)row * D512;
    float* yp = out + (long)row * D512;
    int tid = threadIdx.x;
    float v0 = xp[tid], v1 = xp[tid + 256];
    if (MODE == 1 && (e & 1)) { yp[tid] = v0; yp[tid + 256] = v1; return; }

    __shared__ float red[256];
    red[tid] = v0 + v1; __syncthreads();
    for (int o = 128; o > 0; o >>= 1) { if (tid < o) red[tid] += red[tid + o]; __syncthreads(); }
    float mu = red[0] * (1.0f / 512.0f);
    __syncthreads();
    float d0 = v0 - mu, d1 = v1 - mu;
    red[tid] = d0 * d0 + d1 * d1; __syncthreads();
    for (int o = 128; o > 0; o >>= 1) { if (tid < o) red[tid] += red[tid + o]; __syncthreads(); }
    float rstd = rsqrtf(red[0] * (1.0f / 512.0f) + 1e-5f);

    float y0 = d0 * rstd * g[e * D512 + tid]       + be[e * D512 + tid];
    float y1 = d1 * rstd * g[e * D512 + tid + 256] + be[e * D512 + tid + 256];
    if (MODE == 0) {
        y0 = round_tf32(act_apply(e, y0));
        y1 = round_tf32(act_apply(e, y1));
    }
    yp[tid] = y0; yp[tid + 256] = y1;
}

// ---------------- weighted combine ----------------
__global__ void final_k(const float* __restrict__ z, const float* __restrict__ wgt,
                        float* __restrict__ out)
{
    int t = blockIdx.x, d = threadIdx.x;
    float acc = 0.0f;
#pragma unroll
    for (int k = 0; k < TOPK; k++) {
        int r = t * TOPK + k;
        acc += wgt[r] * z[(long)r * D512 + d];
    }
    out[(long)t * D512 + d] = acc;
}

// ---------------- launch ----------------
template <typename Tv>
static float* symf(Tv& v) { void* p = nullptr; cudaGetSymbolAddress(&p, v); return (float*)p; }
template <typename Tv>
static int* symi(Tv& v) { void* p = nullptr; cudaGetSymbolAddress(&p, v); return (int*)p; }

extern "C" void kernel_launch(void* const* d_in, const int* in_sizes, int n_in,
                              void* d_out, int out_size)
{
    const float* x      = (const float*)d_in[0];
    const float* r_w1   = (const float*)d_in[1];
    const float* r_b1   = (const float*)d_in[2];
    const float* r_w2   = (const float*)d_in[3];
    const float* r_b2   = (const float*)d_in[4];
    const float* r_w3   = (const float*)d_in[5];
    const float* r_b3   = (const float*)d_in[6];
    const float* temp   = (const float*)d_in[7];
    const float* pre_w  = (const float*)d_in[8];
    const float* pre_b  = (const float*)d_in[9];
    const float* pre_g  = (const float*)d_in[10];
    const float* pre_be = (const float*)d_in[11];
    const float* mlp_w1 = (const float*)d_in[12];
    const float* mlp_b1 = (const float*)d_in[13];
    const float* mlp_w2 = (const float*)d_in[14];
    const float* mlp_b2 = (const float*)d_in[15];
    const float* post_w = (const float*)d_in[16];
    const float* post_b = (const float*)d_in[17];
    const float* post_g = (const float*)d_in[18];
    const float* post_be= (const float*)d_in[19];
    float* out = (float*)d_out;

    float* h1     = symf(g_h1);
    float* h2     = symf(g_h2);
    float* scores = symf(g_scores);
    float* lin    = symf(g_lin);
    float* xin    = symf(g_xin);
    float* hid    = symf(g_hid);
    float* mout   = symf(g_mlpout);
    float* zbuf   = symf(g_z);
    float* part   = symf(g_part);
    float* wgt    = symf(g_wgt);
    int* preE  = symi(g_preE);
    int* mlpE  = symi(g_mlpE);
    int* postE = symi(g_postE);
    int* cnt   = symi(g_cnt);
    int* cur   = symi(g_cur);
    int* off   = symi(g_off);
    int* permP = symi(g_permP);
    int* permM = symi(g_permM);
    int* permQ = symi(g_permQ);

    cudaFuncSetAttribute(gemm_tc<0, 0, 1, 0>, cudaFuncAttributeMaxDynamicSharedMemorySize, TC_SMEM_BYTES);
    cudaFuncSetAttribute(gemm_tc<2, 1, 0, 1>, cudaFuncAttributeMaxDynamicSharedMemorySize, TC_SMEM_BYTES);
    cudaFuncSetAttribute(gemm_tc<0, 0, 0, 0>, cudaFuncAttributeMaxDynamicSharedMemorySize, TC_SMEM_BYTES);
    cudaFuncSetAttribute(gemm_tc_sk, cudaFuncAttributeMaxDynamicSharedMemorySize, TC_SMEM_BYTES);

    // zero first (no deps) — keeps the scores GEMM in the ncu capture slot.
    zero_k<<<1, 64>>>(cnt, cur);

    // router (fp32 — top-k selection is precision-critical)
    gemm_k<1><<<dim3(4, 8, 1), 256>>>(x, 512, r_w1, 512, r_b1, h1, 512, 256, 512);
    gemm_k<1><<<dim3(2, 8, 1), 256>>>(h1, 512, r_w2, 256, r_b2, h2, 256, 256, 512);
    gemm_k<0><<<dim3(32, 8, 1), 256>>>(h2, 256, r_w3, 4096, r_b3, scores, 4096, 256, 256);

    // routing
    topk_k<<<256, 256>>>(scores, temp, preE, mlpE, postE, wgt, cnt);
    scan_k<<<1, 32>>>(cnt, off);
    scatter_k<<<8, 256>>>(preE, mlpE, postE, off, cur, permP, permM, permQ);

    // pre experts (X = raw x -> XCVT=1)
    gemm_tc<0, 0, 1, 0><<<dim3(2, 32, 16), 256, TC_SMEM_BYTES>>>(
        x, 512, 3, pre_w, 512L * 512, 512, pre_b, 512, lin, 512, 512, permP, off);
    ln_k<0><<<2048, 256>>>(lin, xin, preE, pre_g, pre_be);   // rounds xin

    // mlp experts: mlp1 grouped, mlp2 split-K (critical-path fix)
    gemm_tc<2, 1, 0, 1><<<dim3(10, 32, 16), 256, TC_SMEM_BYTES>>>(
        xin, 512, 0, mlp_w1, 512L * 2560, 2560, mlp_b1, 2560, hid, 2560, 512, permM, off + 17);
    gemm_tc_sk<<<dim3(2, 32 * MAXCH, 16), 256, TC_SMEM_BYTES>>>(
        hid, 2560, mlp_w2, 2560L * 512, 512, part, permM, off + 17);
    reduce_k<<<2048, 256>>>(part, mlpE, mlp_b2, mout);       // rounds mout

    // post experts (input mout pre-rounded -> XCVT=0)
    gemm_tc<0, 0, 0, 0><<<dim3(2, 32, 16), 256, TC_SMEM_BYTES>>>(
        mout, 512, 0, post_w, 512L * 512, 512, post_b, 512, lin, 512, 512, permQ, off + 34);
    ln_k<1><<<2048, 256>>>(lin, zbuf, postE, post_g, post_be);

    // weighted combine
    final_k<<<256, 512>>>(zbuf, wgt, out);
    (void)in_sizes; (void)n_in; (void)out_size;
}